// round 16
// baseline (speedup 1.0000x reference)
#include <cuda_runtime.h>
#include <math.h>

#define NN 4096          // num nodes
#define FEAT 200
#define OUTC 200
#define OUT_X (NN * OUTC)            // 819200
#define OFF_A (3 * OUT_X)            // A_norm offset in d_out

// ------------------------------------------------------------------
// scratch (static device globals; no allocation allowed)
// ------------------------------------------------------------------
__device__ float g_attr[(size_t)NN * NN];   // 64 MB
__device__ float g_invn[NN];
__device__ float g_dinv[NN];
__device__ float g_diag[NN];
__device__ float g_xs[NN * FEAT];
__device__ float g_tx1[NN * FEAT];
__device__ float g_tx2[NN * FEAT];

// ==================================================================
// GEMM1: attr = sigmoid(X[4096,200] @ W[200,4096] + bias)   (NN layout)
// 128x128 tile, BK=8, 256 threads, 8x8 per thread, double buffered
// ==================================================================
__global__ __launch_bounds__(256) void gemm1_sigmoid(
    const float* __restrict__ X, const float* __restrict__ W,
    const float* __restrict__ bias, float* __restrict__ out)
{
    __shared__ float As[2][8][128];
    __shared__ float Bs[2][8][128];
    const int tid  = threadIdx.x;
    const int row0 = blockIdx.y * 128;
    const int col0 = blockIdx.x * 128;

    const int a_row = tid >> 1;
    const int a_k4  = (tid & 1) << 2;
    const int b_k   = tid >> 5;
    const int b_c4  = (tid & 31) << 2;

    const int warp = tid >> 5, lane = tid & 31;
    const int wm = warp & 1, wn = warp >> 1;
    const int lm = lane & 7, ln = lane >> 3;
    const int tr = wm * 64 + lm * 4;   // rows tr..tr+3, tr+32..tr+35
    const int tc = wn * 32 + ln * 4;   // cols tc..tc+3, tc+16..tc+19

    float acc[8][8];
#pragma unroll
    for (int i = 0; i < 8; i++)
#pragma unroll
        for (int j = 0; j < 8; j++) acc[i][j] = 0.f;

    const int NT = FEAT / 8;   // 25
    float4 ra, rb;

    ra = *(const float4*)&X[(row0 + a_row) * FEAT + a_k4];
    rb = *(const float4*)&W[(size_t)b_k * NN + col0 + b_c4];
    As[0][a_k4 + 0][a_row] = ra.x; As[0][a_k4 + 1][a_row] = ra.y;
    As[0][a_k4 + 2][a_row] = ra.z; As[0][a_k4 + 3][a_row] = ra.w;
    *(float4*)&Bs[0][b_k][b_c4] = rb;
    __syncthreads();

    int buf = 0;
    for (int t = 0; t < NT; t++) {
        if (t + 1 < NT) {
            const int k0 = (t + 1) * 8;
            ra = *(const float4*)&X[(row0 + a_row) * FEAT + k0 + a_k4];
            rb = *(const float4*)&W[(size_t)(k0 + b_k) * NN + col0 + b_c4];
        }
#pragma unroll
        for (int kk = 0; kk < 8; kk++) {
            float4 a0 = *(float4*)&As[buf][kk][tr];
            float4 a1 = *(float4*)&As[buf][kk][tr + 32];
            float4 b0 = *(float4*)&Bs[buf][kk][tc];
            float4 b1 = *(float4*)&Bs[buf][kk][tc + 16];
            float a[8] = {a0.x, a0.y, a0.z, a0.w, a1.x, a1.y, a1.z, a1.w};
            float b[8] = {b0.x, b0.y, b0.z, b0.w, b1.x, b1.y, b1.z, b1.w};
#pragma unroll
            for (int i = 0; i < 8; i++)
#pragma unroll
                for (int j = 0; j < 8; j++)
                    acc[i][j] = fmaf(a[i], b[j], acc[i][j]);
        }
        if (t + 1 < NT) {
            __syncthreads();
            const int nb = buf ^ 1;
            As[nb][a_k4 + 0][a_row] = ra.x; As[nb][a_k4 + 1][a_row] = ra.y;
            As[nb][a_k4 + 2][a_row] = ra.z; As[nb][a_k4 + 3][a_row] = ra.w;
            *(float4*)&Bs[nb][b_k][b_c4] = rb;
            buf = nb;
            __syncthreads();
        }
    }

    float bb[8];
#pragma unroll
    for (int j = 0; j < 8; j++) {
        const int c = col0 + tc + (j < 4 ? j : 12 + j);
        bb[j] = bias[c];
    }
#pragma unroll
    for (int i = 0; i < 8; i++) {
        const int r = row0 + tr + (i < 4 ? i : 28 + i);
        const size_t base = (size_t)r * NN + col0;
        float4 v0, v1;
        v0.x = 1.f / (1.f + expf(-(acc[i][0] + bb[0])));
        v0.y = 1.f / (1.f + expf(-(acc[i][1] + bb[1])));
        v0.z = 1.f / (1.f + expf(-(acc[i][2] + bb[2])));
        v0.w = 1.f / (1.f + expf(-(acc[i][3] + bb[3])));
        v1.x = 1.f / (1.f + expf(-(acc[i][4] + bb[4])));
        v1.y = 1.f / (1.f + expf(-(acc[i][5] + bb[5])));
        v1.z = 1.f / (1.f + expf(-(acc[i][6] + bb[6])));
        v1.w = 1.f / (1.f + expf(-(acc[i][7] + bb[7])));
        *(float4*)&out[base + tc]      = v0;
        *(float4*)&out[base + tc + 16] = v1;
    }
}

// ==================================================================
// row inverse norm: invn[i] = 1 / max(||attr_i||, 1e-8)
// ==================================================================
__global__ void row_invnorm(const float* __restrict__ attr, float* __restrict__ invn)
{
    __shared__ float red[256];
    const int row = blockIdx.x;
    const float4* p = (const float4*)(attr + (size_t)row * NN);
    float s = 0.f;
    for (int i = threadIdx.x; i < NN / 4; i += 256) {
        float4 v = p[i];
        s += v.x * v.x + v.y * v.y + v.z * v.z + v.w * v.w;
    }
    red[threadIdx.x] = s; __syncthreads();
    for (int o = 128; o > 0; o >>= 1) {
        if (threadIdx.x < o) red[threadIdx.x] += red[threadIdx.x + o];
        __syncthreads();
    }
    if (threadIdx.x == 0)
        invn[row] = 1.f / fmaxf(sqrtf(red[0]), 1e-8f);
}

// ==================================================================
// GEMM2 (SYRK): adj = (attr @ attr^T) * invn_i * invn_j
// upper-triangular 128x128 block tiles, mirrored write. NT layout.
// ==================================================================
__global__ __launch_bounds__(256) void gemm2_syrk(
    const float* __restrict__ A, const float* __restrict__ invn,
    float* __restrict__ out)
{
    // decode linear bid -> (br, bc), br <= bc, 32 block rows
    int rem = blockIdx.x, br = 0;
    while (rem >= 32 - br) { rem -= 32 - br; br++; }
    const int bc = br + rem;
    const int row0 = br * 128, col0 = bc * 128;

    __shared__ float As[2][8][128];
    __shared__ float Bs[2][8][128];
    const int tid = threadIdx.x;

    const int l_row = tid >> 1;         // 0..127
    const int l_k4  = (tid & 1) << 2;   // 0 or 4

    const int warp = tid >> 5, lane = tid & 31;
    const int wm = warp & 1, wn = warp >> 1;
    const int lm = lane & 7, ln = lane >> 3;
    const int tr = wm * 64 + lm * 4;
    const int tc = wn * 32 + ln * 4;

    float acc[8][8];
#pragma unroll
    for (int i = 0; i < 8; i++)
#pragma unroll
        for (int j = 0; j < 8; j++) acc[i][j] = 0.f;

    const int NT = NN / 8;   // 512
    float4 ra, rb;

    ra = *(const float4*)&A[(size_t)(row0 + l_row) * NN + l_k4];
    rb = *(const float4*)&A[(size_t)(col0 + l_row) * NN + l_k4];
    As[0][l_k4 + 0][l_row] = ra.x; As[0][l_k4 + 1][l_row] = ra.y;
    As[0][l_k4 + 2][l_row] = ra.z; As[0][l_k4 + 3][l_row] = ra.w;
    Bs[0][l_k4 + 0][l_row] = rb.x; Bs[0][l_k4 + 1][l_row] = rb.y;
    Bs[0][l_k4 + 2][l_row] = rb.z; Bs[0][l_k4 + 3][l_row] = rb.w;
    __syncthreads();

    int buf = 0;
    for (int t = 0; t < NT; t++) {
        if (t + 1 < NT) {
            const int k0 = (t + 1) * 8;
            ra = *(const float4*)&A[(size_t)(row0 + l_row) * NN + k0 + l_k4];
            rb = *(const float4*)&A[(size_t)(col0 + l_row) * NN + k0 + l_k4];
        }
#pragma unroll
        for (int kk = 0; kk < 8; kk++) {
            float4 a0 = *(float4*)&As[buf][kk][tr];
            float4 a1 = *(float4*)&As[buf][kk][tr + 32];
            float4 b0 = *(float4*)&Bs[buf][kk][tc];
            float4 b1 = *(float4*)&Bs[buf][kk][tc + 16];
            float a[8] = {a0.x, a0.y, a0.z, a0.w, a1.x, a1.y, a1.z, a1.w};
            float b[8] = {b0.x, b0.y, b0.z, b0.w, b1.x, b1.y, b1.z, b1.w};
#pragma unroll
            for (int i = 0; i < 8; i++)
#pragma unroll
                for (int j = 0; j < 8; j++)
                    acc[i][j] = fmaf(a[i], b[j], acc[i][j]);
        }
        if (t + 1 < NT) {
            __syncthreads();
            const int nb = buf ^ 1;
            As[nb][l_k4 + 0][l_row] = ra.x; As[nb][l_k4 + 1][l_row] = ra.y;
            As[nb][l_k4 + 2][l_row] = ra.z; As[nb][l_k4 + 3][l_row] = ra.w;
            Bs[nb][l_k4 + 0][l_row] = rb.x; Bs[nb][l_k4 + 1][l_row] = rb.y;
            Bs[nb][l_k4 + 2][l_row] = rb.z; Bs[nb][l_k4 + 3][l_row] = rb.w;
            buf = nb;
            __syncthreads();
        }
    }

    float ir[8], ic[8];
    int rows[8], cols[8];
#pragma unroll
    for (int i = 0; i < 8; i++) {
        rows[i] = row0 + tr + (i < 4 ? i : 28 + i);
        ir[i] = invn[rows[i]];
    }
#pragma unroll
    for (int j = 0; j < 8; j++) {
        cols[j] = col0 + tc + (j < 4 ? j : 12 + j);
        ic[j] = invn[cols[j]];
    }
    // scale
#pragma unroll
    for (int i = 0; i < 8; i++)
#pragma unroll
        for (int j = 0; j < 8; j++)
            acc[i][j] *= ir[i] * ic[j];

    // direct write
#pragma unroll
    for (int i = 0; i < 8; i++) {
        const size_t base = (size_t)rows[i] * NN + col0;
        float4 v0 = make_float4(acc[i][0], acc[i][1], acc[i][2], acc[i][3]);
        float4 v1 = make_float4(acc[i][4], acc[i][5], acc[i][6], acc[i][7]);
        *(float4*)&out[base + tc]      = v0;
        *(float4*)&out[base + tc + 16] = v1;
    }
    // mirrored write
    if (br != bc) {
#pragma unroll
        for (int j = 0; j < 8; j++) {
            const size_t base = (size_t)cols[j] * NN + row0;
            float4 w0 = make_float4(acc[0][j], acc[1][j], acc[2][j], acc[3][j]);
            float4 w1 = make_float4(acc[4][j], acc[5][j], acc[6][j], acc[7][j]);
            *(float4*)&out[base + tr]      = w0;
            *(float4*)&out[base + tr + 32] = w1;
        }
    }
}

// ==================================================================
// row scale: A_norm = adj / rowmax (in place), deg / dinv / diag
// ==================================================================
__global__ void row_scale(float* __restrict__ adj, float* __restrict__ dinv,
                          float* __restrict__ diagA)
{
    __shared__ float red[256];
    const int row = blockIdx.x;
    float* p = adj + (size_t)row * NN;
    float4* p4 = (float4*)p;

    float m = -1e30f;
    for (int i = threadIdx.x; i < NN / 4; i += 256) {
        float4 v = p4[i];
        m = fmaxf(m, fmaxf(fmaxf(v.x, v.y), fmaxf(v.z, v.w)));
    }
    red[threadIdx.x] = m; __syncthreads();
    for (int o = 128; o > 0; o >>= 1) {
        if (threadIdx.x < o) red[threadIdx.x] = fmaxf(red[threadIdx.x], red[threadIdx.x + o]);
        __syncthreads();
    }
    const float inv = 1.f / red[0];
    __syncthreads();

    float s = 0.f;
    for (int i = threadIdx.x; i < NN / 4; i += 256) {
        float4 v = p4[i];
        v.x *= inv; v.y *= inv; v.z *= inv; v.w *= inv;
        p4[i] = v;
        s += v.x + v.y + v.z + v.w;
    }
    red[threadIdx.x] = s; __syncthreads();
    for (int o = 128; o > 0; o >>= 1) {
        if (threadIdx.x < o) red[threadIdx.x] += red[threadIdx.x + o];
        __syncthreads();
    }
    if (threadIdx.x == 0) {
        const float d = p[row];             // scaled diagonal (visible after syncs)
        const float deg = red[0] - d;
        dinv[row] = deg > 0.f ? rsqrtf(deg) : 0.f;
        diagA[row] = d;
    }
}

// ==================================================================
// dst[i,f] = dinv[i] * src[i,f]
// ==================================================================
__global__ void scale_rows(const float* __restrict__ src,
                           const float* __restrict__ dinv,
                           float* __restrict__ dst)
{
    const int idx = blockIdx.x * blockDim.x + threadIdx.x;
    if (idx < NN * FEAT) dst[idx] = dinv[idx / FEAT] * src[idx];
}

// ==================================================================
// propagation: out[i,f] = alpha*dinv[i]*( sum_j A[j,i]*X[j,f] - diagA[i]*X[i,f] )
//              - (addsrc ? addsrc[i,f] : 0)
// BM=128(i), BN=64(f), BK=16, 256 threads, 8x4 per thread
// ==================================================================
__global__ __launch_bounds__(256) void prop_kernel(
    const float* __restrict__ A, const float* __restrict__ X,
    const float* __restrict__ dinv, const float* __restrict__ diagA,
    const float* __restrict__ addsrc, float alpha, float* __restrict__ out)
{
    __shared__ float As[2][16][128];
    __shared__ float Xs[2][16][64];
    const int tid = threadIdx.x;
    const int i0 = blockIdx.x * 128;
    const int f0 = blockIdx.y * 64;

    const int ak = tid >> 4;            // 0..15
    const int ac = (tid & 15) << 2;     // 0..60
    const bool xvalid = (f0 + ac) < OUTC;

    const int ty = tid >> 4;
    const int tx = tid & 15;

    float acc[8][4];
#pragma unroll
    for (int i = 0; i < 8; i++)
#pragma unroll
        for (int j = 0; j < 4; j++) acc[i][j] = 0.f;

    const int NT = NN / 16;   // 256
    float4 ra0, ra1, rx;

    ra0 = *(const float4*)&A[(size_t)ak * NN + i0 + ac];
    ra1 = *(const float4*)&A[(size_t)ak * NN + i0 + ac + 64];
    rx  = xvalid ? *(const float4*)&X[ak * FEAT + f0 + ac]
                 : make_float4(0.f, 0.f, 0.f, 0.f);
    *(float4*)&As[0][ak][ac]      = ra0;
    *(float4*)&As[0][ak][ac + 64] = ra1;
    *(float4*)&Xs[0][ak][ac]      = rx;
    __syncthreads();

    int buf = 0;
    for (int t = 0; t < NT; t++) {
        if (t + 1 < NT) {
            const int j0 = (t + 1) * 16;
            ra0 = *(const float4*)&A[(size_t)(j0 + ak) * NN + i0 + ac];
            ra1 = *(const float4*)&A[(size_t)(j0 + ak) * NN + i0 + ac + 64];
            rx  = xvalid ? *(const float4*)&X[(j0 + ak) * FEAT + f0 + ac]
                         : make_float4(0.f, 0.f, 0.f, 0.f);
        }
#pragma unroll
        for (int kk = 0; kk < 16; kk++) {
            float4 a0 = *(float4*)&As[buf][kk][ty * 8];
            float4 a1 = *(float4*)&As[buf][kk][ty * 8 + 4];
            float4 b  = *(float4*)&Xs[buf][kk][tx * 4];
            float a[8] = {a0.x, a0.y, a0.z, a0.w, a1.x, a1.y, a1.z, a1.w};
            float bv[4] = {b.x, b.y, b.z, b.w};
#pragma unroll
            for (int i = 0; i < 8; i++)
#pragma unroll
                for (int j = 0; j < 4; j++)
                    acc[i][j] = fmaf(a[i], bv[j], acc[i][j]);
        }
        if (t + 1 < NT) {
            __syncthreads();
            const int nb = buf ^ 1;
            *(float4*)&As[nb][ak][ac]      = ra0;
            *(float4*)&As[nb][ak][ac + 64] = ra1;
            *(float4*)&Xs[nb][ak][ac]      = rx;
            buf = nb;
            __syncthreads();
        }
    }

    const int cbase = f0 + tx * 4;
    if (cbase < OUTC) {
#pragma unroll
        for (int ii = 0; ii < 8; ii++) {
            const int r = i0 + ty * 8 + ii;
            const float dv = alpha * dinv[r];
            const float dg = diagA[r];
            float4 xr = *(const float4*)&X[r * FEAT + cbase];
            float4 v;
            v.x = dv * (acc[ii][0] - dg * xr.x);
            v.y = dv * (acc[ii][1] - dg * xr.y);
            v.z = dv * (acc[ii][2] - dg * xr.z);
            v.w = dv * (acc[ii][3] - dg * xr.w);
            if (addsrc) {
                float4 s = *(const float4*)&addsrc[r * FEAT + cbase];
                v.x -= s.x; v.y -= s.y; v.z -= s.z; v.w -= s.w;
            }
            *(float4*)&out[r * OUTC + cbase] = v;
        }
    }
}

// ==================================================================
// small GEMM: C[4096,200] (+)= A[4096,200] @ W[200,200] (+ bias)
// BM=BN=64, BK=8, 256 threads, 4x4 per thread
// ==================================================================
__global__ __launch_bounds__(256) void sgemm_small(
    const float* __restrict__ A, const float* __restrict__ W,
    const float* __restrict__ bias, float* __restrict__ C, int accumulate)
{
    __shared__ float As[2][8][64];
    __shared__ float Ws[2][8][64];
    const int tid = threadIdx.x;
    const int r0 = blockIdx.x * 64;
    const int c0 = blockIdx.y * 64;

    const bool isA = tid < 128;
    const int a_row = tid >> 1;
    const int a_k4  = (tid & 1) << 2;
    const int w_k   = (tid - 128) >> 4;
    const int w_c4  = ((tid - 128) & 15) << 2;
    const bool wvalid = (c0 + w_c4) < OUTC;

    const int ty = tid >> 4;
    const int tx = tid & 15;

    float acc[4][4];
#pragma unroll
    for (int i = 0; i < 4; i++)
#pragma unroll
        for (int j = 0; j < 4; j++) acc[i][j] = 0.f;

    const int NT = FEAT / 8;  // 25
    float4 rv;

    if (isA) {
        rv = *(const float4*)&A[(r0 + a_row) * FEAT + a_k4];
        As[0][a_k4 + 0][a_row] = rv.x; As[0][a_k4 + 1][a_row] = rv.y;
        As[0][a_k4 + 2][a_row] = rv.z; As[0][a_k4 + 3][a_row] = rv.w;
    } else {
        rv = wvalid ? *(const float4*)&W[w_k * OUTC + c0 + w_c4]
                    : make_float4(0.f, 0.f, 0.f, 0.f);
        *(float4*)&Ws[0][w_k][w_c4] = rv;
    }
    __syncthreads();

    int buf = 0;
    for (int t = 0; t < NT; t++) {
        if (t + 1 < NT) {
            const int k0 = (t + 1) * 8;
            if (isA)
                rv = *(const float4*)&A[(r0 + a_row) * FEAT + k0 + a_k4];
            else
                rv = wvalid ? *(const float4*)&W[(k0 + w_k) * OUTC + c0 + w_c4]
                            : make_float4(0.f, 0.f, 0.f, 0.f);
        }
#pragma unroll
        for (int kk = 0; kk < 8; kk++) {
            float4 a = *(float4*)&As[buf][kk][ty * 4];
            float4 b = *(float4*)&Ws[buf][kk][tx * 4];
            float av[4] = {a.x, a.y, a.z, a.w};
            float bv[4] = {b.x, b.y, b.z, b.w};
#pragma unroll
            for (int i = 0; i < 4; i++)
#pragma unroll
                for (int j = 0; j < 4; j++)
                    acc[i][j] = fmaf(av[i], bv[j], acc[i][j]);
        }
        if (t + 1 < NT) {
            __syncthreads();
            const int nb = buf ^ 1;
            if (isA) {
                As[nb][a_k4 + 0][a_row] = rv.x; As[nb][a_k4 + 1][a_row] = rv.y;
                As[nb][a_k4 + 2][a_row] = rv.z; As[nb][a_k4 + 3][a_row] = rv.w;
            } else {
                *(float4*)&Ws[nb][w_k][w_c4] = rv;
            }
            buf = nb;
            __syncthreads();
        }
    }

    const int c = c0 + tx * 4;
    if (c < OUTC) {
        float4 bb = bias ? *(const float4*)&bias[c] : make_float4(0.f, 0.f, 0.f, 0.f);
#pragma unroll
        for (int ii = 0; ii < 4; ii++) {
            const int r = r0 + ty * 4 + ii;
            float4 v = make_float4(acc[ii][0] + bb.x, acc[ii][1] + bb.y,
                                   acc[ii][2] + bb.z, acc[ii][3] + bb.w);
            if (accumulate) {
                float4 old = *(const float4*)&C[r * OUTC + c];
                v.x += old.x; v.y += old.y; v.z += old.z; v.w += old.w;
            }
            *(float4*)&C[r * OUTC + c] = v;
        }
    }
}

// ==================================================================
// BatchNorm (training mode, biased var) over node dim, in place.
// One block per scale; thread c owns column c (coalesced across threads).
// ==================================================================
__global__ void bn_kernel(float* __restrict__ base,
                          const float* __restrict__ gamma,
                          const float* __restrict__ beta)
{
    const int c = threadIdx.x;
    if (c >= OUTC) return;
    float* h = base + (size_t)blockIdx.x * OUT_X;

    double sum = 0.0, sumsq = 0.0;
    for (int r = 0; r < NN; r++) {
        const float v = h[r * OUTC + c];
        sum += v;
        sumsq += (double)v * v;
    }
    const double mu = sum / NN;
    const double var = sumsq / NN - mu * mu;
    const float scale = gamma[c] * rsqrtf((float)var + 1e-5f);
    const float mean = (float)mu;
    const float bt = beta[c];
    for (int r = 0; r < NN; r++) {
        const float v = h[r * OUTC + c];
        h[r * OUTC + c] = scale * (v - mean) + bt;
    }
}

// ==================================================================
// launch
// ==================================================================
extern "C" void kernel_launch(void* const* d_in, const int* in_sizes, int n_in,
                              void* d_out, int out_size)
{
    const float* x     = (const float*)d_in[0];
    const float* ggl_w = (const float*)d_in[1];
    const float* ggl_b = (const float*)d_in[2];
    const float* w1    = (const float*)d_in[3];
    const float* b1    = (const float*)d_in[4];
    const float* w2    = (const float*)d_in[5];
    const float* b2    = (const float*)d_in[6];
    const float* w3    = (const float*)d_in[7];
    const float* b3    = (const float*)d_in[8];
    const float* gamma = (const float*)d_in[9];
    const float* beta  = (const float*)d_in[10];

    float* out = (float*)d_out;
    float* x1o = out;
    float* x2o = out + OUT_X;
    float* x3o = out + 2 * OUT_X;
    float* Anorm = out + OFF_A;

    float* attr; cudaGetSymbolAddress((void**)&attr, g_attr);
    float* invn; cudaGetSymbolAddress((void**)&invn, g_invn);
    float* dinv; cudaGetSymbolAddress((void**)&dinv, g_dinv);
    float* diag; cudaGetSymbolAddress((void**)&diag, g_diag);
    float* xs;   cudaGetSymbolAddress((void**)&xs, g_xs);
    float* tx1;  cudaGetSymbolAddress((void**)&tx1, g_tx1);
    float* tx2;  cudaGetSymbolAddress((void**)&tx2, g_tx2);

    // 1) attr = sigmoid(x @ ggl_w + ggl_b)
    gemm1_sigmoid<<<dim3(32, 32), 256>>>(x, ggl_w, ggl_b, attr);
    // 2) row inverse norms
    row_invnorm<<<NN, 256>>>(attr, invn);
    // 3) adj (cosine sim) -> directly into A_norm output region (symmetric SYRK)
    gemm2_syrk<<<528, 256>>>(attr, invn, Anorm);
    // 4) in-place row-max normalize + deg/dinv/diag
    row_scale<<<NN, 256>>>(Anorm, dinv, diag);
    // 5) xs = dinv * x
    scale_rows<<<(NN * FEAT + 255) / 256, 256>>>(x, dinv, xs);
    // 6) tx1 = -dinv * (A0^T @ xs)
    prop_kernel<<<dim3(32, 4), 256>>>(Anorm, xs, dinv, diag, nullptr, -1.f, tx1);
    // 7) ys = dinv * tx1 (reuse xs)
    scale_rows<<<(NN * FEAT + 255) / 256, 256>>>(tx1, dinv, xs);
    // 8) tx2 = -2*dinv * (A0^T @ ys) - x
    prop_kernel<<<dim3(32, 4), 256>>>(Anorm, xs, dinv, diag, x, -2.f, tx2);
    // 9) Chebyshev linear layers
    sgemm_small<<<dim3(64, 4), 256>>>(x,   w1,                 b1,      x1o, 0);
    sgemm_small<<<dim3(64, 4), 256>>>(x,   w2,                 b2,      x2o, 0);
    sgemm_small<<<dim3(64, 4), 256>>>(tx1, w2 + OUTC * FEAT,   nullptr, x2o, 1);
    sgemm_small<<<dim3(64, 4), 256>>>(x,   w3,                 b3,      x3o, 0);
    sgemm_small<<<dim3(64, 4), 256>>>(tx1, w3 + OUTC * FEAT,   nullptr, x3o, 1);
    sgemm_small<<<dim3(64, 4), 256>>>(tx2, w3 + 2 * OUTC * FEAT, nullptr, x3o, 1);
    // 10) BatchNorm in place on x1,x2,x3
    bn_kernel<<<3, 256>>>(out, gamma, beta);
}

// round 17
// speedup vs baseline: 1.0880x; 1.0880x over previous
#include <cuda_runtime.h>
#include <math.h>

#define NN 4096          // num nodes
#define FEAT 200
#define OUTC 200
#define OUT_X (NN * OUTC)            // 819200
#define OFF_A (3 * OUT_X)            // A_norm offset in d_out

// ------------------------------------------------------------------
// scratch (static device globals; no allocation allowed)
// ------------------------------------------------------------------
__device__ float g_attr[(size_t)NN * NN];   // 64 MB
__device__ float g_invn[NN];
__device__ float g_dinv[NN];
__device__ float g_diag[NN];
__device__ float g_xs[NN * FEAT];
__device__ float g_tx1[NN * FEAT];
__device__ float g_tx2[NN * FEAT];

// ------------------------------------------------------------------
// packed f32x2 helpers (SASS FFMA2 — only reachable via PTX fma.rn.f32x2)
// ------------------------------------------------------------------
typedef unsigned long long u64;

__device__ __forceinline__ u64 dup_f32x2(float v) {
    u64 r;
    asm("mov.b64 %0, {%1, %1};" : "=l"(r) : "f"(v));
    return r;
}
__device__ __forceinline__ void fma_f32x2(u64& d, u64 a, u64 b) {
    asm("fma.rn.f32x2 %0, %1, %2, %0;" : "+l"(d) : "l"(a), "l"(b));
}
__device__ __forceinline__ float2 unpk_f32x2(u64 v) {
    float2 f;
    asm("mov.b64 {%0, %1}, %2;" : "=f"(f.x), "=f"(f.y) : "l"(v));
    return f;
}

// ==================================================================
// GEMM1: attr = sigmoid(X[4096,200] @ W[200,4096] + bias)   (NN layout)
// 128x128 tile, BK=8, 256 threads, 8x8 per thread, double buffered
// inner loop in packed f32x2 (row pairs packed, col broadcast dup'd)
// ==================================================================
__global__ __launch_bounds__(256) void gemm1_sigmoid(
    const float* __restrict__ X, const float* __restrict__ W,
    const float* __restrict__ bias, float* __restrict__ out)
{
    __shared__ float As[2][8][128];
    __shared__ float Bs[2][8][128];
    const int tid  = threadIdx.x;
    const int row0 = blockIdx.y * 128;
    const int col0 = blockIdx.x * 128;

    const int a_row = tid >> 1;
    const int a_k4  = (tid & 1) << 2;
    const int b_k   = tid >> 5;
    const int b_c4  = (tid & 31) << 2;

    const int warp = tid >> 5, lane = tid & 31;
    const int wm = warp & 1, wn = warp >> 1;
    const int lm = lane & 7, ln = lane >> 3;
    const int tr = wm * 64 + lm * 4;   // rows tr..tr+3, tr+32..tr+35
    const int tc = wn * 32 + ln * 4;   // cols tc..tc+3, tc+16..tc+19

    // acc2[ip][j] = (acc[2ip][j], acc[2ip+1][j]) packed along rows
    u64 acc2[4][8];
#pragma unroll
    for (int i = 0; i < 4; i++)
#pragma unroll
        for (int j = 0; j < 8; j++) acc2[i][j] = 0ull;

    const int NT = FEAT / 8;   // 25
    float4 ra, rb;

    ra = *(const float4*)&X[(row0 + a_row) * FEAT + a_k4];
    rb = *(const float4*)&W[(size_t)b_k * NN + col0 + b_c4];
    As[0][a_k4 + 0][a_row] = ra.x; As[0][a_k4 + 1][a_row] = ra.y;
    As[0][a_k4 + 2][a_row] = ra.z; As[0][a_k4 + 3][a_row] = ra.w;
    *(float4*)&Bs[0][b_k][b_c4] = rb;
    __syncthreads();

    int buf = 0;
    for (int t = 0; t < NT; t++) {
        if (t + 1 < NT) {
            const int k0 = (t + 1) * 8;
            ra = *(const float4*)&X[(row0 + a_row) * FEAT + k0 + a_k4];
            rb = *(const float4*)&W[(size_t)(k0 + b_k) * NN + col0 + b_c4];
        }
#pragma unroll
        for (int kk = 0; kk < 8; kk++) {
            ulonglong2 a01 = *(const ulonglong2*)&As[buf][kk][tr];       // rows (0,1),(2,3)
            ulonglong2 a23 = *(const ulonglong2*)&As[buf][kk][tr + 32];  // rows (4,5),(6,7)
            float4 b0 = *(const float4*)&Bs[buf][kk][tc];
            float4 b1 = *(const float4*)&Bs[buf][kk][tc + 16];
            u64 ap[4] = {a01.x, a01.y, a23.x, a23.y};
            u64 bd[8] = {dup_f32x2(b0.x), dup_f32x2(b0.y), dup_f32x2(b0.z), dup_f32x2(b0.w),
                         dup_f32x2(b1.x), dup_f32x2(b1.y), dup_f32x2(b1.z), dup_f32x2(b1.w)};
#pragma unroll
            for (int i = 0; i < 4; i++)
#pragma unroll
                for (int j = 0; j < 8; j++)
                    fma_f32x2(acc2[i][j], ap[i], bd[j]);
        }
        if (t + 1 < NT) {
            __syncthreads();
            const int nb = buf ^ 1;
            As[nb][a_k4 + 0][a_row] = ra.x; As[nb][a_k4 + 1][a_row] = ra.y;
            As[nb][a_k4 + 2][a_row] = ra.z; As[nb][a_k4 + 3][a_row] = ra.w;
            *(float4*)&Bs[nb][b_k][b_c4] = rb;
            buf = nb;
            __syncthreads();
        }
    }

    float acc[8][8];
#pragma unroll
    for (int ip = 0; ip < 4; ip++)
#pragma unroll
        for (int j = 0; j < 8; j++) {
            float2 t2 = unpk_f32x2(acc2[ip][j]);
            acc[2 * ip][j] = t2.x; acc[2 * ip + 1][j] = t2.y;
        }

    float bb[8];
#pragma unroll
    for (int j = 0; j < 8; j++) {
        const int c = col0 + tc + (j < 4 ? j : 12 + j);
        bb[j] = bias[c];
    }
#pragma unroll
    for (int i = 0; i < 8; i++) {
        const int r = row0 + tr + (i < 4 ? i : 28 + i);
        const size_t base = (size_t)r * NN + col0;
        float4 v0, v1;
        v0.x = 1.f / (1.f + expf(-(acc[i][0] + bb[0])));
        v0.y = 1.f / (1.f + expf(-(acc[i][1] + bb[1])));
        v0.z = 1.f / (1.f + expf(-(acc[i][2] + bb[2])));
        v0.w = 1.f / (1.f + expf(-(acc[i][3] + bb[3])));
        v1.x = 1.f / (1.f + expf(-(acc[i][4] + bb[4])));
        v1.y = 1.f / (1.f + expf(-(acc[i][5] + bb[5])));
        v1.z = 1.f / (1.f + expf(-(acc[i][6] + bb[6])));
        v1.w = 1.f / (1.f + expf(-(acc[i][7] + bb[7])));
        *(float4*)&out[base + tc]      = v0;
        *(float4*)&out[base + tc + 16] = v1;
    }
}

// ==================================================================
// row inverse norm: invn[i] = 1 / max(||attr_i||, 1e-8)
// ==================================================================
__global__ void row_invnorm(const float* __restrict__ attr, float* __restrict__ invn)
{
    __shared__ float red[256];
    const int row = blockIdx.x;
    const float4* p = (const float4*)(attr + (size_t)row * NN);
    float s = 0.f;
    for (int i = threadIdx.x; i < NN / 4; i += 256) {
        float4 v = p[i];
        s += v.x * v.x + v.y * v.y + v.z * v.z + v.w * v.w;
    }
    red[threadIdx.x] = s; __syncthreads();
    for (int o = 128; o > 0; o >>= 1) {
        if (threadIdx.x < o) red[threadIdx.x] += red[threadIdx.x + o];
        __syncthreads();
    }
    if (threadIdx.x == 0)
        invn[row] = 1.f / fmaxf(sqrtf(red[0]), 1e-8f);
}

// ==================================================================
// GEMM2 (SYRK): adj = (attr @ attr^T) * invn_i * invn_j
// upper-triangular 128x128 block tiles, mirrored write. NT layout.
// inner loop in packed f32x2
// ==================================================================
__global__ __launch_bounds__(256) void gemm2_syrk(
    const float* __restrict__ A, const float* __restrict__ invn,
    float* __restrict__ out)
{
    // decode linear bid -> (br, bc), br <= bc, 32 block rows
    int rem = blockIdx.x, br = 0;
    while (rem >= 32 - br) { rem -= 32 - br; br++; }
    const int bc = br + rem;
    const int row0 = br * 128, col0 = bc * 128;

    __shared__ float As[2][8][128];
    __shared__ float Bs[2][8][128];
    const int tid = threadIdx.x;

    const int l_row = tid >> 1;         // 0..127
    const int l_k4  = (tid & 1) << 2;   // 0 or 4

    const int warp = tid >> 5, lane = tid & 31;
    const int wm = warp & 1, wn = warp >> 1;
    const int lm = lane & 7, ln = lane >> 3;
    const int tr = wm * 64 + lm * 4;
    const int tc = wn * 32 + ln * 4;

    u64 acc2[4][8];
#pragma unroll
    for (int i = 0; i < 4; i++)
#pragma unroll
        for (int j = 0; j < 8; j++) acc2[i][j] = 0ull;

    const int NT = NN / 8;   // 512
    float4 ra, rb;

    ra = *(const float4*)&A[(size_t)(row0 + l_row) * NN + l_k4];
    rb = *(const float4*)&A[(size_t)(col0 + l_row) * NN + l_k4];
    As[0][l_k4 + 0][l_row] = ra.x; As[0][l_k4 + 1][l_row] = ra.y;
    As[0][l_k4 + 2][l_row] = ra.z; As[0][l_k4 + 3][l_row] = ra.w;
    Bs[0][l_k4 + 0][l_row] = rb.x; Bs[0][l_k4 + 1][l_row] = rb.y;
    Bs[0][l_k4 + 2][l_row] = rb.z; Bs[0][l_k4 + 3][l_row] = rb.w;
    __syncthreads();

    int buf = 0;
    for (int t = 0; t < NT; t++) {
        if (t + 1 < NT) {
            const int k0 = (t + 1) * 8;
            ra = *(const float4*)&A[(size_t)(row0 + l_row) * NN + k0 + l_k4];
            rb = *(const float4*)&A[(size_t)(col0 + l_row) * NN + k0 + l_k4];
        }
#pragma unroll
        for (int kk = 0; kk < 8; kk++) {
            ulonglong2 a01 = *(const ulonglong2*)&As[buf][kk][tr];
            ulonglong2 a23 = *(const ulonglong2*)&As[buf][kk][tr + 32];
            float4 b0 = *(const float4*)&Bs[buf][kk][tc];
            float4 b1 = *(const float4*)&Bs[buf][kk][tc + 16];
            u64 ap[4] = {a01.x, a01.y, a23.x, a23.y};
            u64 bd[8] = {dup_f32x2(b0.x), dup_f32x2(b0.y), dup_f32x2(b0.z), dup_f32x2(b0.w),
                         dup_f32x2(b1.x), dup_f32x2(b1.y), dup_f32x2(b1.z), dup_f32x2(b1.w)};
#pragma unroll
            for (int i = 0; i < 4; i++)
#pragma unroll
                for (int j = 0; j < 8; j++)
                    fma_f32x2(acc2[i][j], ap[i], bd[j]);
        }
        if (t + 1 < NT) {
            __syncthreads();
            const int nb = buf ^ 1;
            As[nb][l_k4 + 0][l_row] = ra.x; As[nb][l_k4 + 1][l_row] = ra.y;
            As[nb][l_k4 + 2][l_row] = ra.z; As[nb][l_k4 + 3][l_row] = ra.w;
            Bs[nb][l_k4 + 0][l_row] = rb.x; Bs[nb][l_k4 + 1][l_row] = rb.y;
            Bs[nb][l_k4 + 2][l_row] = rb.z; Bs[nb][l_k4 + 3][l_row] = rb.w;
            buf = nb;
            __syncthreads();
        }
    }

    float acc[8][8];
#pragma unroll
    for (int ip = 0; ip < 4; ip++)
#pragma unroll
        for (int j = 0; j < 8; j++) {
            float2 t2 = unpk_f32x2(acc2[ip][j]);
            acc[2 * ip][j] = t2.x; acc[2 * ip + 1][j] = t2.y;
        }

    float ir[8], ic[8];
    int rows[8], cols[8];
#pragma unroll
    for (int i = 0; i < 8; i++) {
        rows[i] = row0 + tr + (i < 4 ? i : 28 + i);
        ir[i] = invn[rows[i]];
    }
#pragma unroll
    for (int j = 0; j < 8; j++) {
        cols[j] = col0 + tc + (j < 4 ? j : 12 + j);
        ic[j] = invn[cols[j]];
    }
    // scale
#pragma unroll
    for (int i = 0; i < 8; i++)
#pragma unroll
        for (int j = 0; j < 8; j++)
            acc[i][j] *= ir[i] * ic[j];

    // direct write
#pragma unroll
    for (int i = 0; i < 8; i++) {
        const size_t base = (size_t)rows[i] * NN + col0;
        float4 v0 = make_float4(acc[i][0], acc[i][1], acc[i][2], acc[i][3]);
        float4 v1 = make_float4(acc[i][4], acc[i][5], acc[i][6], acc[i][7]);
        *(float4*)&out[base + tc]      = v0;
        *(float4*)&out[base + tc + 16] = v1;
    }
    // mirrored write
    if (br != bc) {
#pragma unroll
        for (int j = 0; j < 8; j++) {
            const size_t base = (size_t)cols[j] * NN + row0;
            float4 w0 = make_float4(acc[0][j], acc[1][j], acc[2][j], acc[3][j]);
            float4 w1 = make_float4(acc[4][j], acc[5][j], acc[6][j], acc[7][j]);
            *(float4*)&out[base + tr]      = w0;
            *(float4*)&out[base + tr + 32] = w1;
        }
    }
}

// ==================================================================
// row scale: A_norm = adj / rowmax (in place), deg / dinv / diag
// ==================================================================
__global__ void row_scale(float* __restrict__ adj, float* __restrict__ dinv,
                          float* __restrict__ diagA)
{
    __shared__ float red[256];
    const int row = blockIdx.x;
    float* p = adj + (size_t)row * NN;
    float4* p4 = (float4*)p;

    float m = -1e30f;
    for (int i = threadIdx.x; i < NN / 4; i += 256) {
        float4 v = p4[i];
        m = fmaxf(m, fmaxf(fmaxf(v.x, v.y), fmaxf(v.z, v.w)));
    }
    red[threadIdx.x] = m; __syncthreads();
    for (int o = 128; o > 0; o >>= 1) {
        if (threadIdx.x < o) red[threadIdx.x] = fmaxf(red[threadIdx.x], red[threadIdx.x + o]);
        __syncthreads();
    }
    const float inv = 1.f / red[0];
    __syncthreads();

    float s = 0.f;
    for (int i = threadIdx.x; i < NN / 4; i += 256) {
        float4 v = p4[i];
        v.x *= inv; v.y *= inv; v.z *= inv; v.w *= inv;
        p4[i] = v;
        s += v.x + v.y + v.z + v.w;
    }
    red[threadIdx.x] = s; __syncthreads();
    for (int o = 128; o > 0; o >>= 1) {
        if (threadIdx.x < o) red[threadIdx.x] += red[threadIdx.x + o];
        __syncthreads();
    }
    if (threadIdx.x == 0) {
        const float d = p[row];             // scaled diagonal (visible after syncs)
        const float deg = red[0] - d;
        dinv[row] = deg > 0.f ? rsqrtf(deg) : 0.f;
        diagA[row] = d;
    }
}

// ==================================================================
// dst[i,f] = dinv[i] * src[i,f]
// ==================================================================
__global__ void scale_rows(const float* __restrict__ src,
                           const float* __restrict__ dinv,
                           float* __restrict__ dst)
{
    const int idx = blockIdx.x * blockDim.x + threadIdx.x;
    if (idx < NN * FEAT) dst[idx] = dinv[idx / FEAT] * src[idx];
}

// ==================================================================
// propagation: out[i,f] = alpha*dinv[i]*( sum_j A[j,i]*X[j,f] - diagA[i]*X[i,f] )
//              - (addsrc ? addsrc[i,f] : 0)
// BM=128(i), BN=64(f), BK=16, 256 threads, 8x4 per thread, f32x2 inner loop
// ==================================================================
__global__ __launch_bounds__(256) void prop_kernel(
    const float* __restrict__ A, const float* __restrict__ X,
    const float* __restrict__ dinv, const float* __restrict__ diagA,
    const float* __restrict__ addsrc, float alpha, float* __restrict__ out)
{
    __shared__ float As[2][16][128];
    __shared__ float Xs[2][16][64];
    const int tid = threadIdx.x;
    const int i0 = blockIdx.x * 128;
    const int f0 = blockIdx.y * 64;

    const int ak = tid >> 4;            // 0..15
    const int ac = (tid & 15) << 2;     // 0..60
    const bool xvalid = (f0 + ac) < OUTC;

    const int ty = tid >> 4;
    const int tx = tid & 15;

    // acc2[ip][j] = rows (2ip, 2ip+1) packed
    u64 acc2[4][4];
#pragma unroll
    for (int i = 0; i < 4; i++)
#pragma unroll
        for (int j = 0; j < 4; j++) acc2[i][j] = 0ull;

    const int NT = NN / 16;   // 256
    float4 ra0, ra1, rx;

    ra0 = *(const float4*)&A[(size_t)ak * NN + i0 + ac];
    ra1 = *(const float4*)&A[(size_t)ak * NN + i0 + ac + 64];
    rx  = xvalid ? *(const float4*)&X[ak * FEAT + f0 + ac]
                 : make_float4(0.f, 0.f, 0.f, 0.f);
    *(float4*)&As[0][ak][ac]      = ra0;
    *(float4*)&As[0][ak][ac + 64] = ra1;
    *(float4*)&Xs[0][ak][ac]      = rx;
    __syncthreads();

    int buf = 0;
    for (int t = 0; t < NT; t++) {
        if (t + 1 < NT) {
            const int j0 = (t + 1) * 16;
            ra0 = *(const float4*)&A[(size_t)(j0 + ak) * NN + i0 + ac];
            ra1 = *(const float4*)&A[(size_t)(j0 + ak) * NN + i0 + ac + 64];
            rx  = xvalid ? *(const float4*)&X[(j0 + ak) * FEAT + f0 + ac]
                         : make_float4(0.f, 0.f, 0.f, 0.f);
        }
#pragma unroll
        for (int kk = 0; kk < 16; kk++) {
            ulonglong2 a01 = *(const ulonglong2*)&As[buf][kk][ty * 8];      // rows (0,1),(2,3)
            ulonglong2 a23 = *(const ulonglong2*)&As[buf][kk][ty * 8 + 4];  // rows (4,5),(6,7)
            float4 b  = *(const float4*)&Xs[buf][kk][tx * 4];
            u64 ap[4] = {a01.x, a01.y, a23.x, a23.y};
            u64 bd[4] = {dup_f32x2(b.x), dup_f32x2(b.y), dup_f32x2(b.z), dup_f32x2(b.w)};
#pragma unroll
            for (int i = 0; i < 4; i++)
#pragma unroll
                for (int j = 0; j < 4; j++)
                    fma_f32x2(acc2[i][j], ap[i], bd[j]);
        }
        if (t + 1 < NT) {
            __syncthreads();
            const int nb = buf ^ 1;
            *(float4*)&As[nb][ak][ac]      = ra0;
            *(float4*)&As[nb][ak][ac + 64] = ra1;
            *(float4*)&Xs[nb][ak][ac]      = rx;
            buf = nb;
            __syncthreads();
        }
    }

    float acc[8][4];
#pragma unroll
    for (int ip = 0; ip < 4; ip++)
#pragma unroll
        for (int j = 0; j < 4; j++) {
            float2 t2 = unpk_f32x2(acc2[ip][j]);
            acc[2 * ip][j] = t2.x; acc[2 * ip + 1][j] = t2.y;
        }

    const int cbase = f0 + tx * 4;
    if (cbase < OUTC) {
#pragma unroll
        for (int ii = 0; ii < 8; ii++) {
            const int r = i0 + ty * 8 + ii;
            const float dv = alpha * dinv[r];
            const float dg = diagA[r];
            float4 xr = *(const float4*)&X[r * FEAT + cbase];
            float4 v;
            v.x = dv * (acc[ii][0] - dg * xr.x);
            v.y = dv * (acc[ii][1] - dg * xr.y);
            v.z = dv * (acc[ii][2] - dg * xr.z);
            v.w = dv * (acc[ii][3] - dg * xr.w);
            if (addsrc) {
                float4 s = *(const float4*)&addsrc[r * FEAT + cbase];
                v.x -= s.x; v.y -= s.y; v.z -= s.z; v.w -= s.w;
            }
            *(float4*)&out[r * OUTC + cbase] = v;
        }
    }
}

// ==================================================================
// small GEMM: C[4096,200] (+)= A[4096,200] @ W[200,200] (+ bias)
// BM=BN=64, BK=8, 256 threads, 4x4 per thread
// ==================================================================
__global__ __launch_bounds__(256) void sgemm_small(
    const float* __restrict__ A, const float* __restrict__ W,
    const float* __restrict__ bias, float* __restrict__ C, int accumulate)
{
    __shared__ float As[2][8][64];
    __shared__ float Ws[2][8][64];
    const int tid = threadIdx.x;
    const int r0 = blockIdx.x * 64;
    const int c0 = blockIdx.y * 64;

    const bool isA = tid < 128;
    const int a_row = tid >> 1;
    const int a_k4  = (tid & 1) << 2;
    const int w_k   = (tid - 128) >> 4;
    const int w_c4  = ((tid - 128) & 15) << 2;
    const bool wvalid = (c0 + w_c4) < OUTC;

    const int ty = tid >> 4;
    const int tx = tid & 15;

    float acc[4][4];
#pragma unroll
    for (int i = 0; i < 4; i++)
#pragma unroll
        for (int j = 0; j < 4; j++) acc[i][j] = 0.f;

    const int NT = FEAT / 8;  // 25
    float4 rv;

    if (isA) {
        rv = *(const float4*)&A[(r0 + a_row) * FEAT + a_k4];
        As[0][a_k4 + 0][a_row] = rv.x; As[0][a_k4 + 1][a_row] = rv.y;
        As[0][a_k4 + 2][a_row] = rv.z; As[0][a_k4 + 3][a_row] = rv.w;
    } else {
        rv = wvalid ? *(const float4*)&W[w_k * OUTC + c0 + w_c4]
                    : make_float4(0.f, 0.f, 0.f, 0.f);
        *(float4*)&Ws[0][w_k][w_c4] = rv;
    }
    __syncthreads();

    int buf = 0;
    for (int t = 0; t < NT; t++) {
        if (t + 1 < NT) {
            const int k0 = (t + 1) * 8;
            if (isA)
                rv = *(const float4*)&A[(r0 + a_row) * FEAT + k0 + a_k4];
            else
                rv = wvalid ? *(const float4*)&W[(k0 + w_k) * OUTC + c0 + w_c4]
                            : make_float4(0.f, 0.f, 0.f, 0.f);
        }
#pragma unroll
        for (int kk = 0; kk < 8; kk++) {
            float4 a = *(float4*)&As[buf][kk][ty * 4];
            float4 b = *(float4*)&Ws[buf][kk][tx * 4];
            float av[4] = {a.x, a.y, a.z, a.w};
            float bv[4] = {b.x, b.y, b.z, b.w};
#pragma unroll
            for (int i = 0; i < 4; i++)
#pragma unroll
                for (int j = 0; j < 4; j++)
                    acc[i][j] = fmaf(av[i], bv[j], acc[i][j]);
        }
        if (t + 1 < NT) {
            __syncthreads();
            const int nb = buf ^ 1;
            if (isA) {
                As[nb][a_k4 + 0][a_row] = rv.x; As[nb][a_k4 + 1][a_row] = rv.y;
                As[nb][a_k4 + 2][a_row] = rv.z; As[nb][a_k4 + 3][a_row] = rv.w;
            } else {
                *(float4*)&Ws[nb][w_k][w_c4] = rv;
            }
            buf = nb;
            __syncthreads();
        }
    }

    const int c = c0 + tx * 4;
    if (c < OUTC) {
        float4 bb = bias ? *(const float4*)&bias[c] : make_float4(0.f, 0.f, 0.f, 0.f);
#pragma unroll
        for (int ii = 0; ii < 4; ii++) {
            const int r = r0 + ty * 4 + ii;
            float4 v = make_float4(acc[ii][0] + bb.x, acc[ii][1] + bb.y,
                                   acc[ii][2] + bb.z, acc[ii][3] + bb.w);
            if (accumulate) {
                float4 old = *(const float4*)&C[r * OUTC + c];
                v.x += old.x; v.y += old.y; v.z += old.z; v.w += old.w;
            }
            *(float4*)&C[r * OUTC + c] = v;
        }
    }
}

// ==================================================================
// BatchNorm (training mode, biased var) over node dim, in place.
// One block per scale; thread c owns column c (coalesced across threads).
// ==================================================================
__global__ void bn_kernel(float* __restrict__ base,
                          const float* __restrict__ gamma,
                          const float* __restrict__ beta)
{
    const int c = threadIdx.x;
    if (c >= OUTC) return;
    float* h = base + (size_t)blockIdx.x * OUT_X;

    double sum = 0.0, sumsq = 0.0;
    for (int r = 0; r < NN; r++) {
        const float v = h[r * OUTC + c];
        sum += v;
        sumsq += (double)v * v;
    }
    const double mu = sum / NN;
    const double var = sumsq / NN - mu * mu;
    const float scale = gamma[c] * rsqrtf((float)var + 1e-5f);
    const float mean = (float)mu;
    const float bt = beta[c];
    for (int r = 0; r < NN; r++) {
        const float v = h[r * OUTC + c];
        h[r * OUTC + c] = scale * (v - mean) + bt;
    }
}

// ==================================================================
// launch
// ==================================================================
extern "C" void kernel_launch(void* const* d_in, const int* in_sizes, int n_in,
                              void* d_out, int out_size)
{
    const float* x     = (const float*)d_in[0];
    const float* ggl_w = (const float*)d_in[1];
    const float* ggl_b = (const float*)d_in[2];
    const float* w1    = (const float*)d_in[3];
    const float* b1    = (const float*)d_in[4];
    const float* w2    = (const float*)d_in[5];
    const float* b2    = (const float*)d_in[6];
    const float* w3    = (const float*)d_in[7];
    const float* b3    = (const float*)d_in[8];
    const float* gamma = (const float*)d_in[9];
    const float* beta  = (const float*)d_in[10];

    float* out = (float*)d_out;
    float* x1o = out;
    float* x2o = out + OUT_X;
    float* x3o = out + 2 * OUT_X;
    float* Anorm = out + OFF_A;

    float* attr; cudaGetSymbolAddress((void**)&attr, g_attr);
    float* invn; cudaGetSymbolAddress((void**)&invn, g_invn);
    float* dinv; cudaGetSymbolAddress((void**)&dinv, g_dinv);
    float* diag; cudaGetSymbolAddress((void**)&diag, g_diag);
    float* xs;   cudaGetSymbolAddress((void**)&xs, g_xs);
    float* tx1;  cudaGetSymbolAddress((void**)&tx1, g_tx1);
    float* tx2;  cudaGetSymbolAddress((void**)&tx2, g_tx2);

    // 1) attr = sigmoid(x @ ggl_w + ggl_b)
    gemm1_sigmoid<<<dim3(32, 32), 256>>>(x, ggl_w, ggl_b, attr);
    // 2) row inverse norms
    row_invnorm<<<NN, 256>>>(attr, invn);
    // 3) adj (cosine sim) -> directly into A_norm output region (symmetric SYRK)
    gemm2_syrk<<<528, 256>>>(attr, invn, Anorm);
    // 4) in-place row-max normalize + deg/dinv/diag
    row_scale<<<NN, 256>>>(Anorm, dinv, diag);
    // 5) xs = dinv * x
    scale_rows<<<(NN * FEAT + 255) / 256, 256>>>(x, dinv, xs);
    // 6) tx1 = -dinv * (A0^T @ xs)
    prop_kernel<<<dim3(32, 4), 256>>>(Anorm, xs, dinv, diag, nullptr, -1.f, tx1);
    // 7) ys = dinv * tx1 (reuse xs)
    scale_rows<<<(NN * FEAT + 255) / 256, 256>>>(tx1, dinv, xs);
    // 8) tx2 = -2*dinv * (A0^T @ ys) - x
    prop_kernel<<<dim3(32, 4), 256>>>(Anorm, xs, dinv, diag, x, -2.f, tx2);
    // 9) Chebyshev linear layers
    sgemm_small<<<dim3(64, 4), 256>>>(x,   w1,                 b1,      x1o, 0);
    sgemm_small<<<dim3(64, 4), 256>>>(x,   w2,                 b2,      x2o, 0);
    sgemm_small<<<dim3(64, 4), 256>>>(tx1, w2 + OUTC * FEAT,   nullptr, x2o, 1);
    sgemm_small<<<dim3(64, 4), 256>>>(x,   w3,                 b3,      x3o, 0);
    sgemm_small<<<dim3(64, 4), 256>>>(tx1, w3 + OUTC * FEAT,   nullptr, x3o, 1);
    sgemm_small<<<dim3(64, 4), 256>>>(tx2, w3 + 2 * OUTC * FEAT, nullptr, x3o, 1);
    // 10) BatchNorm in place on x1,x2,x3
    bn_kernel<<<3, 256>>>(out, gamma, beta);
}